// round 1
// baseline (speedup 1.0000x reference)
#include <cuda_runtime.h>

#define G_ 16384
#define N_ 32
#define D_ 128
#define R_ 32
#define H_ 256
#define O_ 64

// Mt[r][o] = sum_h Wl[o,h] * V[h,r]   (transposed so epilogue reads are coalesced)
__device__ float g_Mt[R_ * O_];

__global__ void prep_kernel(const float* __restrict__ V, const float* __restrict__ Wl) {
    int t = blockIdx.x * blockDim.x + threadIdx.x;  // 0..2047
    int r = t >> 6;
    int o = t & 63;
    const float4* Wl4 = (const float4*)(Wl + o * H_);
    float acc = 0.f;
#pragma unroll 4
    for (int h4 = 0; h4 < H_ / 4; ++h4) {
        float4 w = Wl4[h4];
        acc += w.x * V[(h4 * 4 + 0) * R_ + r];
        acc += w.y * V[(h4 * 4 + 1) * R_ + r];
        acc += w.z * V[(h4 * 4 + 2) * R_ + r];
        acc += w.w * V[(h4 * 4 + 3) * R_ + r];
    }
    g_Mt[r * O_ + o] = acc;
}

// One CTA per graph, 64 threads.
// Thread layout: r = tid & 31 (output column of feat), half = tid >> 5 owns 16 node rows.
// feat[n][r] accumulated as packed f32x2 over k-pairs (k-contiguous -> no pack instrs).
__global__ void __launch_bounds__(64) main_kernel(const float* __restrict__ hin,
                                                  const float* __restrict__ W,
                                                  const float* __restrict__ bl,
                                                  float* __restrict__ out) {
    __shared__ __align__(16) float sh[N_ * D_];     // 32 x 128 h tile (row-major)
    __shared__ __align__(16) float sWt[R_ * 132];   // W transposed, rows padded to 132 floats
    __shared__ float sRed[2][R_];
    __shared__ float sPooled[R_];

    const int tid = threadIdx.x;
    const int g = blockIdx.x;

    // ---- stage h tile (16 KB), coalesced float4 ----
    {
        const float4* hg = (const float4*)(hin + (size_t)g * (N_ * D_));
        float4* sh4 = (float4*)sh;
#pragma unroll
        for (int j = 0; j < 16; ++j) sh4[tid + j * 64] = hg[tid + j * 64];
    }
    // ---- stage W transposed: sWt[r][k] = W[k][r], row stride 132 (16B aligned, conflict-free) ----
    {
        const float4* Wg4 = (const float4*)W;
#pragma unroll
        for (int j = 0; j < 16; ++j) {
            int i4 = tid + j * 64;          // float4 index into W (k-major, 32 per row)
            float4 w4 = Wg4[i4];
            int k = i4 >> 3;                // i4*4 / 32
            int r0 = (i4 & 7) * 4;
            sWt[(r0 + 0) * 132 + k] = w4.x;
            sWt[(r0 + 1) * 132 + k] = w4.y;
            sWt[(r0 + 2) * 132 + k] = w4.z;
            sWt[(r0 + 3) * 132 + k] = w4.w;
        }
    }
    __syncthreads();

    const int r = tid & 31;
    const int n0 = (tid >> 5) * 16;

    unsigned long long acc[16];
#pragma unroll
    for (int j = 0; j < 16; ++j) acc[j] = 0ULL;   // {0.f, 0.f}

    const float* wrow = sWt + r * 132;
    const float* hbase = sh + n0 * D_;

#pragma unroll 2
    for (int k4 = 0; k4 < 32; ++k4) {
        ulonglong2 wv = *(const ulonglong2*)(wrow + k4 * 4);   // {w[k],w[k+1]},{w[k+2],w[k+3]}
#pragma unroll
        for (int j = 0; j < 16; ++j) {
            ulonglong2 hv = *(const ulonglong2*)(hbase + j * D_ + k4 * 4);
            asm("fma.rn.f32x2 %0, %1, %2, %0;" : "+l"(acc[j]) : "l"(hv.x), "l"(wv.x));
            asm("fma.rn.f32x2 %0, %1, %2, %0;" : "+l"(acc[j]) : "l"(hv.y), "l"(wv.y));
        }
    }

    // horizontal add of the two packed halves, then product over this thread's 16 nodes
    float p = 1.f;
#pragma unroll
    for (int j = 0; j < 16; ++j) {
        float lo, hi;
        asm("mov.b64 {%0, %1}, %2;" : "=f"(lo), "=f"(hi) : "l"(acc[j]));
        p *= (lo + hi);
    }

    sRed[tid >> 5][r] = p;
    __syncthreads();
    if (tid < 32) sPooled[tid] = sRed[0][tid] * sRed[1][tid];
    __syncthreads();

    // ---- epilogue: score[o] = bl[o] + sum_r pooled[r] * Mt[r][o]  (o = tid, 64 outputs) ----
    float s = bl[tid];
#pragma unroll
    for (int rr = 0; rr < R_; ++rr)
        s = fmaf(sPooled[rr], g_Mt[rr * O_ + tid], s);
    out[(size_t)g * O_ + tid] = s;
}

extern "C" void kernel_launch(void* const* d_in, const int* in_sizes, int n_in,
                              void* d_out, int out_size) {
    const float* h  = (const float*)d_in[0];
    const float* W  = (const float*)d_in[1];
    const float* V  = (const float*)d_in[2];
    const float* Wl = (const float*)d_in[3];
    const float* bl = (const float*)d_in[4];
    float* out = (float*)d_out;

    prep_kernel<<<8, 256>>>(V, Wl);
    main_kernel<<<G_, 64>>>(h, W, bl, out);
}

// round 3
// speedup vs baseline: 1.1984x; 1.1984x over previous
#include <cuda_runtime.h>

#define G_ 16384
#define N_ 32
#define D_ 128
#define R_ 32
#define H_ 256
#define O_ 64

// Prepared operands (written by prep_kernel each launch; deterministic)
__device__ float  g_Wt[R_ * D_];      // Wt[r][k] = W[k][r]
__device__ float2 g_Mtp[R_ * 32];     // g_Mtp[r][o2] = { Mt[r][o2], Mt[r][o2+32] },  Mt = (Wl@V)^T

__global__ void prep_kernel(const float* __restrict__ V,
                            const float* __restrict__ Wl,
                            const float* __restrict__ W) {
    int t = blockIdx.x * blockDim.x + threadIdx.x;   // 0..4095
    // transpose W: 4096 elements
    int k = t >> 5, r = t & 31;
    g_Wt[r * D_ + k] = W[k * R_ + r];
    // Mt[r][o] = sum_h Wl[o][h] * V[h][r], packed over o-pairs (o, o+32)
    if (t < 1024) {
        int rr = t >> 5, o2 = t & 31;
        float a0 = 0.f, a1 = 0.f;
        for (int hh = 0; hh < H_; ++hh) {
            float v = V[hh * R_ + rr];
            a0 += Wl[o2 * H_ + hh] * v;
            a1 += Wl[(o2 + 32) * H_ + hh] * v;
        }
        g_Mtp[rr * 32 + o2] = make_float2(a0, a1);
    }
}

// Shared memory layout (floats), all rows strided 132 floats = 33 x 16B (odd -> conflict-free)
//   sWt   : [0, 4224)              32 x 132
//   sH[w] : 4224 + w*4224          per-warp 32 x 132 h tile
//   sPool : 4224*5 + w*32          per-warp pooled[32]
#define SMEM_FLOATS (4224 * 5 + 4 * 32)

extern __shared__ float smem[];

// 1 warp = 1 graph. Lane = ni*4 + rj: ni in 0..7 (node group), rj in 0..3 (r group).
// Lane owns nodes {ni + 8n : n=0..3} and r-values {4t + rj : t=0..7}.
__global__ void __launch_bounds__(128) main_kernel(const float* __restrict__ hin,
                                                   const float* __restrict__ bl,
                                                   float* __restrict__ out) {
    const int tid = threadIdx.x;
    const int w = tid >> 5;
    const int lane = tid & 31;

    float* sWt = smem;
    float* sH = smem + 4224 + w * 4224;
    float* sPool = smem + 4224 * 5 + w * 32;

    // ---- stage Wt (whole CTA): 1024 float4, padded rows ----
    {
        const float4* src = (const float4*)g_Wt;
#pragma unroll
        for (int j = 0; j < 8; ++j) {
            int i4 = j * 128 + tid;
            int r = i4 >> 5, c = i4 & 31;
            *(float4*)(sWt + r * 132 + c * 4) = src[i4];
        }
    }

    // ---- stage h tile (warp-private): coalesced LDG.128 -> conflict-free STS.128 ----
    const int g = blockIdx.x * 4 + w;
    {
        const float4* hg = (const float4*)(hin + (size_t)g * (N_ * D_));
#pragma unroll
        for (int j = 0; j < 32; ++j) {
            float4 v = hg[j * 32 + lane];
            *(float4*)(sH + j * 132 + lane * 4) = v;   // row j, cols 4*lane..
        }
    }
    __syncthreads();   // Wt visible to all warps (also orders the warp-private h)

    const int ni = lane >> 2;
    const int rj = lane & 3;

    // packed accumulators: acc[n][t] = {even-k partial, odd-k partial} of feat[node][r]
    unsigned long long acc[4][8];
#pragma unroll
    for (int n = 0; n < 4; ++n)
#pragma unroll
        for (int t = 0; t < 8; ++t) acc[n][t] = 0ULL;

#pragma unroll 2
    for (int k4 = 0; k4 < 32; ++k4) {
        ulonglong2 wv[8];
#pragma unroll
        for (int t = 0; t < 8; ++t)
            wv[t] = *(const ulonglong2*)(sWt + (4 * t + rj) * 132 + k4 * 4);
        ulonglong2 hv[4];
#pragma unroll
        for (int n = 0; n < 4; ++n)
            hv[n] = *(const ulonglong2*)(sH + (ni + 8 * n) * 132 + k4 * 4);
#pragma unroll
        for (int n = 0; n < 4; ++n)
#pragma unroll
            for (int t = 0; t < 8; ++t) {
                asm("fma.rn.f32x2 %0, %1, %2, %0;" : "+l"(acc[n][t]) : "l"(hv[n].x), "l"(wv[t].x));
                asm("fma.rn.f32x2 %0, %1, %2, %0;" : "+l"(acc[n][t]) : "l"(hv[n].y), "l"(wv[t].y));
            }
    }

    // ---- horizontal add + product over this lane's 4 nodes ----
    float p[8];
#pragma unroll
    for (int t = 0; t < 8; ++t) p[t] = 1.f;
#pragma unroll
    for (int n = 0; n < 4; ++n)
#pragma unroll
        for (int t = 0; t < 8; ++t) {
            float lo, hi;
            asm("mov.b64 {%0, %1}, %2;" : "=f"(lo), "=f"(hi) : "l"(acc[n][t]));
            p[t] *= (lo + hi);
        }

    // ---- product across the 8 node-groups (lane bits 2..4) ----
#pragma unroll
    for (int m = 4; m <= 16; m <<= 1)
#pragma unroll
        for (int t = 0; t < 8; ++t)
            p[t] *= __shfl_xor_sync(0xffffffffu, p[t], m);

    if (ni == 0) {
#pragma unroll
        for (int t = 0; t < 8; ++t) sPool[4 * t + rj] = p[t];
    }
    __syncwarp();

    // ---- epilogue: score[o] = bl[o] + sum_r pooled[r] * Mt[r][o], lane -> (o, o+32) ----
    unsigned long long s2;
    {
        float b0 = bl[lane], b1 = bl[lane + 32];
        asm("mov.b64 %0, {%1, %2};" : "=l"(s2) : "f"(b0), "f"(b1));
    }
#pragma unroll
    for (int r = 0; r < R_; ++r) {
        float pv = sPool[r];
        unsigned long long pp, mm;
        asm("mov.b64 %0, {%1, %1};" : "=l"(pp) : "f"(pv));
        mm = __ldg((const unsigned long long*)&g_Mtp[r * 32 + lane]);
        asm("fma.rn.f32x2 %0, %1, %2, %0;" : "+l"(s2) : "l"(pp), "l"(mm));
    }
    float s0, s1;
    asm("mov.b64 {%0, %1}, %2;" : "=f"(s0), "=f"(s1) : "l"(s2));
    out[(size_t)g * O_ + lane] = s0;
    out[(size_t)g * O_ + lane + 32] = s1;
}

extern "C" void kernel_launch(void* const* d_in, const int* in_sizes, int n_in,
                              void* d_out, int out_size) {
    const float* h  = (const float*)d_in[0];
    const float* W  = (const float*)d_in[1];
    const float* V  = (const float*)d_in[2];
    const float* Wl = (const float*)d_in[3];
    const float* bl = (const float*)d_in[4];
    float* out = (float*)d_out;

    static int attr_set = 0;
    if (!attr_set) {
        cudaFuncSetAttribute(main_kernel, cudaFuncAttributeMaxDynamicSharedMemorySize,
                             SMEM_FLOATS * sizeof(float));
        attr_set = 1;
    }

    prep_kernel<<<16, 256>>>(V, Wl, W);
    main_kernel<<<G_ / 4, 128, SMEM_FLOATS * sizeof(float)>>>(h, bl, out);
}

// round 5
// speedup vs baseline: 1.3370x; 1.1156x over previous
#include <cuda_runtime.h>

#define G_ 16384
#define D_ 128
#define R_ 32
#define H_ 256
#define O_ 64

// Prepared operands (written by prep_kernel every launch; deterministic)
__device__ float  g_Wt[R_ * D_];      // Wt[r][k] = W[k][r]
__device__ float2 g_Mtp[R_ * 32];     // g_Mtp[r][o2] = { Mt[r][o2], Mt[r][o2+32] }, Mt=(Wl@V)^T

// grid 64 x 256 = 16384 threads
__global__ void prep_kernel(const float* __restrict__ V,
                            const float* __restrict__ Wl,
                            const float* __restrict__ W) {
    int t = blockIdx.x * blockDim.x + threadIdx.x;
    if (t < 4096) {                     // transpose W
        int k = t >> 5, r = t & 31;
        g_Wt[r * D_ + k] = W[k * R_ + r];
    }
    // Mt[rr][rem] = sum_h Wl[rem][h] * V[h][rr]; 2048 outputs x 8-way h-split
    int u = t >> 3, seg = t & 7;        // u: output unit, seg: h segment (lanes 0..7)
    int rr = u >> 6, rem = u & 63;
    const float* wl = Wl + rem * H_ + seg * 32;
    const float* vp = V + seg * 32 * R_ + rr;
    float acc = 0.f;
#pragma unroll
    for (int i = 0; i < 32; ++i)
        acc = fmaf(wl[i], vp[i * R_], acc);
#pragma unroll
    for (int m = 1; m <= 4; m <<= 1)
        acc += __shfl_xor_sync(0xffffffffu, acc, m);
    if (seg == 0)
        ((float*)g_Mtp)[rr * 64 + (rem & 31) * 2 + (rem >> 5)] = acc;
}

// Shared layout (floats), rows padded to 132 (33 x 16B, odd -> conflict-free):
//   sWt       [0, 4224)
//   sH[8]     4224 + t*4224     (warp w owns tiles 2w, 2w+1 : its two graphs)
//   sPool     4224*9 + w*64     (2 x 32 per warp)
#define SMEM_FLOATS (4224 * 9 + 4 * 64)

extern __shared__ float smem[];

// CTA = 4 warps; warp = 2 graphs. Lane = ni*4+rj (ni 0..7 node-group, rj 0..3 r-group).
// Lane tile: 2 graphs x 4 nodes {ni+8n} x 8 r {4t+rj}  ->  64 f32x2 accumulators.
__global__ void __launch_bounds__(128, 1) main_kernel(const float* __restrict__ hin,
                                                      const float* __restrict__ bl,
                                                      float* __restrict__ out) {
    const int tid = threadIdx.x;
    const int w = tid >> 5;
    const int lane = tid & 31;

    float* sWt = smem;
    float* sH0 = smem + 4224 * (1 + 2 * w);
    float* sH1 = sH0 + 4224;
    float* sPool0 = smem + 4224 * 9 + w * 64;
    float* sPool1 = sPool0 + 32;

    // ---- stage Wt (whole CTA) ----
    {
        const float4* src = (const float4*)g_Wt;
#pragma unroll
        for (int j = 0; j < 8; ++j) {
            int i4 = j * 128 + tid;
            int r = i4 >> 5, c = i4 & 31;
            *(float4*)(sWt + r * 132 + c * 4) = src[i4];
        }
    }
    // ---- stage the warp's two h tiles: coalesced LDG.128 -> conflict-free STS.128 ----
    const int g0 = blockIdx.x * 8 + 2 * w;
    {
        const float4* hg0 = (const float4*)(hin + (size_t)g0 * (32 * D_));
        const float4* hg1 = hg0 + (32 * D_ / 4);
#pragma unroll
        for (int j = 0; j < 32; ++j) {
            *(float4*)(sH0 + j * 132 + lane * 4) = hg0[j * 32 + lane];
            *(float4*)(sH1 + j * 132 + lane * 4) = hg1[j * 32 + lane];
        }
    }
    __syncthreads();

    const int ni = lane >> 2;
    const int rj = lane & 3;

    unsigned long long acc0[4][8], acc1[4][8];
#pragma unroll
    for (int n = 0; n < 4; ++n)
#pragma unroll
        for (int t = 0; t < 8; ++t) { acc0[n][t] = 0ULL; acc1[n][t] = 0ULL; }

    const float* wbase = sWt + rj * 132;
    const float* h0 = sH0 + ni * 132;
    const float* h1 = sH1 + ni * 132;

#pragma unroll 1
    for (int k4 = 0; k4 < 32; ++k4) {
        const int kc = k4 * 4;
        ulonglong2 wv[8];
#pragma unroll
        for (int t = 0; t < 8; ++t)
            wv[t] = *(const ulonglong2*)(wbase + t * (4 * 132) + kc);
        {
            ulonglong2 hv[4];
#pragma unroll
            for (int n = 0; n < 4; ++n)
                hv[n] = *(const ulonglong2*)(h0 + n * (8 * 132) + kc);
#pragma unroll
            for (int n = 0; n < 4; ++n)
#pragma unroll
                for (int t = 0; t < 8; ++t) {
                    asm("fma.rn.f32x2 %0, %1, %2, %0;" : "+l"(acc0[n][t]) : "l"(hv[n].x), "l"(wv[t].x));
                    asm("fma.rn.f32x2 %0, %1, %2, %0;" : "+l"(acc0[n][t]) : "l"(hv[n].y), "l"(wv[t].y));
                }
        }
        {
            ulonglong2 hv[4];
#pragma unroll
            for (int n = 0; n < 4; ++n)
                hv[n] = *(const ulonglong2*)(h1 + n * (8 * 132) + kc);
#pragma unroll
            for (int n = 0; n < 4; ++n)
#pragma unroll
                for (int t = 0; t < 8; ++t) {
                    asm("fma.rn.f32x2 %0, %1, %2, %0;" : "+l"(acc1[n][t]) : "l"(hv[n].x), "l"(wv[t].x));
                    asm("fma.rn.f32x2 %0, %1, %2, %0;" : "+l"(acc1[n][t]) : "l"(hv[n].y), "l"(wv[t].y));
                }
        }
    }

    // ---- horizontal add + product over this lane's 4 nodes (per graph) ----
    float p0[8], p1[8];
#pragma unroll
    for (int t = 0; t < 8; ++t) { p0[t] = 1.f; p1[t] = 1.f; }
#pragma unroll
    for (int n = 0; n < 4; ++n)
#pragma unroll
        for (int t = 0; t < 8; ++t) {
            float lo, hi;
            asm("mov.b64 {%0, %1}, %2;" : "=f"(lo), "=f"(hi) : "l"(acc0[n][t]));
            p0[t] *= (lo + hi);
            asm("mov.b64 {%0, %1}, %2;" : "=f"(lo), "=f"(hi) : "l"(acc1[n][t]));
            p1[t] *= (lo + hi);
        }

    // ---- product across 8 node-groups (lane bits 2..4) ----
#pragma unroll
    for (int m = 4; m <= 16; m <<= 1)
#pragma unroll
        for (int t = 0; t < 8; ++t) {
            p0[t] *= __shfl_xor_sync(0xffffffffu, p0[t], m);
            p1[t] *= __shfl_xor_sync(0xffffffffu, p1[t], m);
        }

    if (ni == 0) {
#pragma unroll
        for (int t = 0; t < 8; ++t) {
            sPool0[4 * t + rj] = p0[t];
            sPool1[4 * t + rj] = p1[t];
        }
    }
    __syncwarp();

    // ---- epilogue: score[o] = bl[o] + sum_r pooled[r]*Mt[r][o]; lane -> (o, o+32) ----
    float b0 = bl[lane], b1 = bl[lane + 32];
#pragma unroll 1
    for (int gg = 0; gg < 2; ++gg) {
        const float* pool = gg ? sPool1 : sPool0;
        unsigned long long s2;
        asm("mov.b64 %0, {%1, %2};" : "=l"(s2) : "f"(b0), "f"(b1));
#pragma unroll
        for (int r = 0; r < R_; ++r) {
            float pv = pool[r];
            unsigned long long pp, mm;
            asm("mov.b64 %0, {%1, %1};" : "=l"(pp) : "f"(pv));
            mm = __ldg((const unsigned long long*)&g_Mtp[r * 32 + lane]);
            asm("fma.rn.f32x2 %0, %1, %2, %0;" : "+l"(s2) : "l"(pp), "l"(mm));
        }
        float s0, s1;
        asm("mov.b64 {%0, %1}, %2;" : "=f"(s0), "=f"(s1) : "l"(s2));
        out[(size_t)(g0 + gg) * O_ + lane] = s0;
        out[(size_t)(g0 + gg) * O_ + lane + 32] = s1;
    }
}

extern "C" void kernel_launch(void* const* d_in, const int* in_sizes, int n_in,
                              void* d_out, int out_size) {
    const float* h  = (const float*)d_in[0];
    const float* W  = (const float*)d_in[1];
    const float* V  = (const float*)d_in[2];
    const float* Wl = (const float*)d_in[3];
    const float* bl = (const float*)d_in[4];
    float* out = (float*)d_out;

    static int attr_set = 0;
    if (!attr_set) {
        cudaFuncSetAttribute(main_kernel, cudaFuncAttributeMaxDynamicSharedMemorySize,
                             SMEM_FLOATS * sizeof(float));
        attr_set = 1;
    }

    prep_kernel<<<64, 256>>>(V, Wl, W);
    main_kernel<<<G_ / 8, 128, SMEM_FLOATS * sizeof(float)>>>(h, bl, out);
}

// round 7
// speedup vs baseline: 1.6707x; 1.2496x over previous
#include <cuda_runtime.h>

#define G_ 16384
#define D_ 128
#define R_ 32
#define H_ 256
#define O_ 64

// Prepared operands (written by prep_kernel every launch; deterministic)
__device__ float  g_Wt[R_ * D_];      // Wt[r][k] = W[k][r]
__device__ float2 g_Mtp[R_ * 32];     // g_Mtp[r][o2] = { Mt[r][o2], Mt[r][o2+32] }, Mt=(Wl@V)^T

// grid 64 x 256 = 16384 threads
__global__ void prep_kernel(const float* __restrict__ V,
                            const float* __restrict__ Wl,
                            const float* __restrict__ W) {
    int t = blockIdx.x * blockDim.x + threadIdx.x;
    if (t < 4096) {                     // transpose W
        int k = t >> 5, r = t & 31;
        g_Wt[r * D_ + k] = W[k * R_ + r];
    }
    // Mt[rr][rem] = sum_h Wl[rem][h] * V[h][rr]; 2048 outputs x 8-way h-split
    int u = t >> 3, seg = t & 7;
    int rr = u >> 6, rem = u & 63;
    const float* wl = Wl + rem * H_ + seg * 32;
    const float* vp = V + seg * 32 * R_ + rr;
    float acc = 0.f;
#pragma unroll
    for (int i = 0; i < 32; ++i)
        acc = fmaf(wl[i], vp[i * R_], acc);
#pragma unroll
    for (int m = 1; m <= 4; m <<= 1)
        acc += __shfl_xor_sync(0xffffffffu, acc, m);
    if (seg == 0)
        ((float*)g_Mtp)[rr * 64 + (rem & 31) * 2 + (rem >> 5)] = acc;
}

// Shared layout (floats):
//   sWt        [0, 4224)                 32 x 132  (full K, rows 33x16B odd stride)
//   sH chunks  4224 + t*2176             8 x (32 x 68)  k-half chunks, rows 17x16B odd stride
//   sPool      4224 + 8*2176 + w*64      2 x 32 per warp
// Total 21888 floats = 87.5 KB -> 2 CTAs (8 warps) per SM.
#define SMEM_FLOATS (4224 + 8 * 2176 + 4 * 64)

extern __shared__ float smem[];

// CTA = 4 warps; warp = 2 graphs; K processed in 2 stages of 64.
// Lane = ni*4+rj (ni 0..7 node-group, rj 0..3 r-group).
// Lane tile: 2 graphs x 4 nodes {ni+8n} x 8 r {4t+rj}  ->  64 f32x2 accumulators.
__global__ void __launch_bounds__(128, 2) main_kernel(const float* __restrict__ hin,
                                                      const float* __restrict__ bl,
                                                      float* __restrict__ out) {
    const int tid = threadIdx.x;
    const int w = tid >> 5;
    const int lane = tid & 31;

    float* sWt = smem;
    float* sH0 = smem + 4224 + (2 * w) * 2176;
    float* sH1 = sH0 + 2176;
    float* sPool0 = smem + 4224 + 8 * 2176 + w * 64;
    float* sPool1 = sPool0 + 32;

    // ---- stage Wt (whole CTA, full K) ----
    {
        const float4* src = (const float4*)g_Wt;
#pragma unroll
        for (int j = 0; j < 8; ++j) {
            int i4 = j * 128 + tid;
            int r = i4 >> 5, c = i4 & 31;
            *(float4*)(sWt + r * 132 + c * 4) = src[i4];
        }
    }

    const int g0 = blockIdx.x * 8 + 2 * w;
    const float* hg0 = hin + (size_t)g0 * (32 * D_);
    const float* hg1 = hg0 + 32 * D_;

    const int ni = lane >> 2;
    const int rj = lane & 3;
    const int srow = (lane >> 4);        // staging: half-warp -> row parity
    const int sc4 = (lane & 15) * 4;     // staging: float offset within 64-col chunk

    unsigned long long acc0[4][8], acc1[4][8];
#pragma unroll
    for (int n = 0; n < 4; ++n)
#pragma unroll
        for (int t = 0; t < 8; ++t) { acc0[n][t] = 0ULL; acc1[n][t] = 0ULL; }

    const float* wcol = sWt + rj * 132;
    const float* h0 = sH0 + ni * 68;
    const float* h1 = sH1 + ni * 68;

    bool first = true;
#pragma unroll 1
    for (int s = 0; s < 2; ++s) {
        // ---- stage this warp's two h k-half chunks (warp-private) ----
#pragma unroll
        for (int j = 0; j < 16; ++j) {
            int row = 2 * j + srow;
            float4 v0 = *(const float4*)(hg0 + row * D_ + s * 64 + sc4);
            float4 v1 = *(const float4*)(hg1 + row * D_ + s * 64 + sc4);
            *(float4*)(sH0 + row * 68 + sc4) = v0;
            *(float4*)(sH1 + row * 68 + sc4) = v1;
        }
        if (first) { __syncthreads(); first = false; }  // Wt + first chunks visible
        else       { __syncwarp(); }                    // chunks warp-private

        const float* wbase = wcol + s * 64;
#pragma unroll 1
        for (int k4 = 0; k4 < 16; ++k4) {
            const int kc = k4 * 4;
            ulonglong2 wv[8];
#pragma unroll
            for (int t = 0; t < 8; ++t)
                wv[t] = *(const ulonglong2*)(wbase + t * (4 * 132) + kc);
            {
                ulonglong2 hv[4];
#pragma unroll
                for (int n = 0; n < 4; ++n)
                    hv[n] = *(const ulonglong2*)(h0 + n * (8 * 68) + kc);
#pragma unroll
                for (int n = 0; n < 4; ++n)
#pragma unroll
                    for (int t = 0; t < 8; ++t) {
                        asm("fma.rn.f32x2 %0, %1, %2, %0;" : "+l"(acc0[n][t]) : "l"(hv[n].x), "l"(wv[t].x));
                        asm("fma.rn.f32x2 %0, %1, %2, %0;" : "+l"(acc0[n][t]) : "l"(hv[n].y), "l"(wv[t].y));
                    }
            }
            {
                ulonglong2 hv[4];
#pragma unroll
                for (int n = 0; n < 4; ++n)
                    hv[n] = *(const ulonglong2*)(h1 + n * (8 * 68) + kc);
#pragma unroll
                for (int n = 0; n < 4; ++n)
#pragma unroll
                    for (int t = 0; t < 8; ++t) {
                        asm("fma.rn.f32x2 %0, %1, %2, %0;" : "+l"(acc1[n][t]) : "l"(hv[n].x), "l"(wv[t].x));
                        asm("fma.rn.f32x2 %0, %1, %2, %0;" : "+l"(acc1[n][t]) : "l"(hv[n].y), "l"(wv[t].y));
                    }
            }
        }
        __syncwarp();   // all lanes done reading chunk before next-stage overwrite
    }

    // ---- horizontal add + product over this lane's 4 nodes (per graph) ----
    float p0[8], p1[8];
#pragma unroll
    for (int t = 0; t < 8; ++t) { p0[t] = 1.f; p1[t] = 1.f; }
#pragma unroll
    for (int n = 0; n < 4; ++n)
#pragma unroll
        for (int t = 0; t < 8; ++t) {
            float lo, hi;
            asm("mov.b64 {%0, %1}, %2;" : "=f"(lo), "=f"(hi) : "l"(acc0[n][t]));
            p0[t] *= (lo + hi);
            asm("mov.b64 {%0, %1}, %2;" : "=f"(lo), "=f"(hi) : "l"(acc1[n][t]));
            p1[t] *= (lo + hi);
        }

    // ---- product across 8 node-groups (lane bits 2..4) ----
#pragma unroll
    for (int m = 4; m <= 16; m <<= 1)
#pragma unroll
        for (int t = 0; t < 8; ++t) {
            p0[t] *= __shfl_xor_sync(0xffffffffu, p0[t], m);
            p1[t] *= __shfl_xor_sync(0xffffffffu, p1[t], m);
        }

    if (ni == 0) {
#pragma unroll
        for (int t = 0; t < 8; ++t) {
            sPool0[4 * t + rj] = p0[t];
            sPool1[4 * t + rj] = p1[t];
        }
    }
    __syncwarp();

    // ---- epilogue: score[o] = bl[o] + sum_r pooled[r]*Mt[r][o]; lane -> (o, o+32) ----
    float b0 = bl[lane], b1 = bl[lane + 32];
#pragma unroll 1
    for (int gg = 0; gg < 2; ++gg) {
        const float* pool = gg ? sPool1 : sPool0;
        unsigned long long s2;
        asm("mov.b64 %0, {%1, %2};" : "=l"(s2) : "f"(b0), "f"(b1));
#pragma unroll
        for (int r = 0; r < R_; ++r) {
            float pv = pool[r];
            unsigned long long pp, mm;
            asm("mov.b64 %0, {%1, %1};" : "=l"(pp) : "f"(pv));
            mm = __ldg((const unsigned long long*)&g_Mtp[r * 32 + lane]);
            asm("fma.rn.f32x2 %0, %1, %2, %0;" : "+l"(s2) : "l"(pp), "l"(mm));
        }
        float s0, s1;
        asm("mov.b64 {%0, %1}, %2;" : "=f"(s0), "=f"(s1) : "l"(s2));
        out[(size_t)(g0 + gg) * O_ + lane] = s0;
        out[(size_t)(g0 + gg) * O_ + lane + 32] = s1;
    }
}

extern "C" void kernel_launch(void* const* d_in, const int* in_sizes, int n_in,
                              void* d_out, int out_size) {
    const float* h  = (const float*)d_in[0];
    const float* W  = (const float*)d_in[1];
    const float* V  = (const float*)d_in[2];
    const float* Wl = (const float*)d_in[3];
    const float* bl = (const float*)d_in[4];
    float* out = (float*)d_out;

    static int attr_set = 0;
    if (!attr_set) {
        cudaFuncSetAttribute(main_kernel, cudaFuncAttributeMaxDynamicSharedMemorySize,
                             SMEM_FLOATS * sizeof(float));
        attr_set = 1;
    }

    prep_kernel<<<64, 256>>>(V, Wl, W);
    main_kernel<<<G_ / 8, 128, SMEM_FLOATS * sizeof(float)>>>(h, bl, out);
}

// round 9
// speedup vs baseline: 2.4673x; 1.4768x over previous
#include <cuda_runtime.h>
#include <cstdint>

#define G_ 16384
#define D_ 128
#define R_ 32
#define H_ 256
#define O_ 64

// B fragments, fragment-ordered: idx = (nt*16 + ks)*32 + lane, payload {bhi0,bhi1,blo0,blo1}
__device__ uint4  g_Bfrag[64 * 32];
__device__ float2 g_Mtp[R_ * 32];   // {Mt[r][o], Mt[r][o+32]}, Mt=(Wl@V)^T

__device__ __forceinline__ uint32_t cvt_tf32(float x) {
    uint32_t u;
    asm("cvt.rna.tf32.f32 %0, %1;" : "=r"(u) : "f"(x));
    return u;
}

// grid 64 x 256 = 16384 threads
__global__ void prep_kernel(const float* __restrict__ V,
                            const float* __restrict__ Wl,
                            const float* __restrict__ W) {
    int t = blockIdx.x * blockDim.x + threadIdx.x;
    if (t < 2048) {
        // fragment (nt, ks, lane): b0 = W[ks*8 + (l&3)][nt*8 + (l>>2)], b1 = +4 k-rows
        int l = t & 31, ks = (t >> 5) & 15, nt = t >> 9;
        int k0 = ks * 8 + (l & 3), n = nt * 8 + (l >> 2);
        float b0 = W[k0 * R_ + n];
        float b1 = W[(k0 + 4) * R_ + n];
        uint32_t h0 = __float_as_uint(b0) & 0xFFFFE000u;
        uint32_t h1 = __float_as_uint(b1) & 0xFFFFE000u;
        uint4 pk;
        pk.x = h0;
        pk.y = h1;
        pk.z = cvt_tf32(b0 - __uint_as_float(h0));
        pk.w = cvt_tf32(b1 - __uint_as_float(h1));
        g_Bfrag[t] = pk;
    }
    // Mt[rr][rem] = sum_h Wl[rem][h] * V[h][rr]; 2048 outputs x 8-way h split
    int u = t >> 3, seg = t & 7;
    int rr = u >> 6, rem = u & 63;
    const float* wl = Wl + rem * H_ + seg * 32;
    const float* vp = V + seg * 32 * R_ + rr;
    float acc = 0.f;
#pragma unroll
    for (int i = 0; i < 32; ++i)
        acc = fmaf(wl[i], vp[i * R_], acc);
#pragma unroll
    for (int m = 1; m <= 4; m <<= 1)
        acc += __shfl_xor_sync(0xffffffffu, acc, m);
    if (seg == 0)
        ((float*)g_Mtp)[rr * 64 + (rem & 31) * 2 + (rem >> 5)] = acc;
}

// ---- smem layout (bytes) ----
//  sB    [0, 32768)                      64x32 uint4 B fragments
//  sA    32768 + w*18432                 per warp: (buf*2+graph)*4608, each 32 rows x 36 floats
//  sPool 180224 + w*256                  per warp: 2 graphs x 32 floats
#define SA_OFF   32768
#define POOL_OFF 180224
#define SM_TOTAL 182272

__device__ __forceinline__ uint32_t smem_u32(const void* p) {
    uint32_t a;
    asm("{ .reg .u64 t; cvta.to.shared.u64 t, %1; cvt.u32.u64 %0, t; }" : "=r"(a) : "l"(p));
    return a;
}

#define MMA(c, a0, a1, a2, a3, b0, b1)                                        \
    asm volatile("mma.sync.aligned.m16n8k8.row.col.f32.tf32.tf32.f32 "        \
                 "{%0,%1,%2,%3}, {%4,%5,%6,%7}, {%8,%9}, {%0,%1,%2,%3};"      \
                 : "+f"(c[0]), "+f"(c[1]), "+f"(c[2]), "+f"(c[3])             \
                 : "r"(a0), "r"(a1), "r"(a2), "r"(a3), "r"(b0), "r"(b1))

#define CPASYNC(dst, src) \
    asm volatile("cp.async.cg.shared.global [%0], [%1], 16;" :: "r"(dst), "l"(src))

extern __shared__ __align__(16) char smc[];

// CTA = 8 warps, warp = 2 graphs. grid = 1024.
__global__ void __launch_bounds__(256, 1)
main_kernel(const float* __restrict__ hin, const float* __restrict__ bl,
            float* __restrict__ out) {
    const int t = threadIdx.x;
    const int w = t >> 5;
    const int l = t & 31;

    // ---- stage B fragments (whole CTA) ----
    {
        uint4* sB = (uint4*)smc;
#pragma unroll
        for (int j = 0; j < 8; ++j) sB[j * 256 + t] = g_Bfrag[j * 256 + t];
    }
    __syncthreads();

    float* sA = (float*)(smc + SA_OFF + w * 18432);
    float* sPool = (float*)(smc + POOL_OFF) + w * 64;
    const uint32_t sAu = smem_u32(sA);

    const int g0 = blockIdx.x * 16 + w * 2;
    const float* hb[2];
    hb[0] = hin + (size_t)g0 * (32 * D_);
    hb[1] = hb[0] + 32 * D_;

    const int r4 = l >> 2, lc = l & 3;
    const int srow = l >> 3, scol = (l & 7) * 4;   // staging pattern

    float c[2][2][4][4];
#pragma unroll
    for (int g = 0; g < 2; ++g)
#pragma unroll
        for (int mt = 0; mt < 2; ++mt)
#pragma unroll
            for (int nt = 0; nt < 4; ++nt)
#pragma unroll
                for (int i = 0; i < 4; ++i) c[g][mt][nt][i] = 0.f;

    // ---- stage quarter 0 into buf 0 ----
#pragma unroll
    for (int g = 0; g < 2; ++g) {
        uint32_t dbase = sAu + g * 4608;
        const float* src = hb[g];
#pragma unroll
        for (int j = 0; j < 8; ++j) {
            int row = j * 4 + srow;
            CPASYNC(dbase + (row * 36 + scol) * 4, src + row * D_ + scol);
        }
    }
    asm volatile("cp.async.commit_group;" ::: "memory");

#pragma unroll 1
    for (int q = 0; q < 4; ++q) {
        const int buf = q & 1;
        if (q < 3) {   // prefetch next quarter into other buffer
            const int nbuf = buf ^ 1;
#pragma unroll
            for (int g = 0; g < 2; ++g) {
                uint32_t dbase = sAu + (nbuf * 2 + g) * 4608;
                const float* src = hb[g] + (q + 1) * 32;
#pragma unroll
                for (int j = 0; j < 8; ++j) {
                    int row = j * 4 + srow;
                    CPASYNC(dbase + (row * 36 + scol) * 4, src + row * D_ + scol);
                }
            }
            asm volatile("cp.async.commit_group;" ::: "memory");
            asm volatile("cp.async.wait_group 1;" ::: "memory");
        } else {
            asm volatile("cp.async.wait_group 0;" ::: "memory");
        }
        __syncwarp();

        const float* A[2];
        A[0] = sA + (buf * 2 + 0) * 1152;
        A[1] = sA + (buf * 2 + 1) * 1152;

#pragma unroll
        for (int ks = 0; ks < 4; ++ks) {
            const int kc = ks * 8 + lc;
            // B fragments (shared by both graphs): one LDS.128 per n-tile
            uint4 bv[4];
#pragma unroll
            for (int nt = 0; nt < 4; ++nt)
                bv[nt] = ((const uint4*)smc)[nt * 512 + (q * 4 + ks) * 32 + l];

#pragma unroll
            for (int g = 0; g < 2; ++g) {
                uint32_t ahi[2][4], alo[2][4];
#pragma unroll
                for (int mt = 0; mt < 2; ++mt) {
                    const float* ab = A[g] + (mt * 16 + r4) * 36;
                    float a0 = ab[kc];
                    float a1 = ab[8 * 36 + kc];
                    float a2 = ab[kc + 4];
                    float a3 = ab[8 * 36 + kc + 4];
                    ahi[mt][0] = __float_as_uint(a0) & 0xFFFFE000u;
                    ahi[mt][1] = __float_as_uint(a1) & 0xFFFFE000u;
                    ahi[mt][2] = __float_as_uint(a2) & 0xFFFFE000u;
                    ahi[mt][3] = __float_as_uint(a3) & 0xFFFFE000u;
                    alo[mt][0] = cvt_tf32(a0 - __uint_as_float(ahi[mt][0]));
                    alo[mt][1] = cvt_tf32(a1 - __uint_as_float(ahi[mt][1]));
                    alo[mt][2] = cvt_tf32(a2 - __uint_as_float(ahi[mt][2]));
                    alo[mt][3] = cvt_tf32(a3 - __uint_as_float(ahi[mt][3]));
                }
#pragma unroll
                for (int mt = 0; mt < 2; ++mt)
#pragma unroll
                    for (int nt = 0; nt < 4; ++nt) {
                        MMA(c[g][mt][nt], ahi[mt][0], ahi[mt][1], ahi[mt][2], ahi[mt][3],
                            bv[nt].x, bv[nt].y);
                        MMA(c[g][mt][nt], ahi[mt][0], ahi[mt][1], ahi[mt][2], ahi[mt][3],
                            bv[nt].z, bv[nt].w);
                        MMA(c[g][mt][nt], alo[mt][0], alo[mt][1], alo[mt][2], alo[mt][3],
                            bv[nt].x, bv[nt].y);
                    }
            }
        }
        __syncwarp();
    }

    // ---- pooling: product over nodes ----
    // C frag rows per thread: {r4, r4+8} per m-tile -> nodes {r4, r4+8, r4+16, r4+24}.
    // cols: nt*8 + 2*lc + {0,1}.
#pragma unroll
    for (int g = 0; g < 2; ++g) {
        float pv[4][2];
#pragma unroll
        for (int nt = 0; nt < 4; ++nt)
#pragma unroll
            for (int b = 0; b < 2; ++b)
                pv[nt][b] = c[g][0][nt][b] * c[g][0][nt][b + 2] *
                            c[g][1][nt][b] * c[g][1][nt][b + 2];
#pragma unroll
        for (int m = 4; m <= 16; m <<= 1)
#pragma unroll
            for (int nt = 0; nt < 4; ++nt)
#pragma unroll
                for (int b = 0; b < 2; ++b)
                    pv[nt][b] *= __shfl_xor_sync(0xffffffffu, pv[nt][b], m);
        if (r4 == 0) {
#pragma unroll
            for (int nt = 0; nt < 4; ++nt) {
                sPool[g * 32 + nt * 8 + 2 * lc + 0] = pv[nt][0];
                sPool[g * 32 + nt * 8 + 2 * lc + 1] = pv[nt][1];
            }
        }
    }
    __syncwarp();

    // ---- epilogue: score[o] = bl[o] + sum_r pooled[r]*Mt[r][o]; lane -> (o, o+32) ----
    float b0 = bl[l], b1 = bl[l + 32];
#pragma unroll 1
    for (int g = 0; g < 2; ++g) {
        const float* pool = sPool + g * 32;
        unsigned long long s2;
        asm("mov.b64 %0, {%1, %2};" : "=l"(s2) : "f"(b0), "f"(b1));
#pragma unroll
        for (int r = 0; r < R_; ++r) {
            float pvv = pool[r];
            unsigned long long pp, mm;
            asm("mov.b64 %0, {%1, %1};" : "=l"(pp) : "f"(pvv));
            mm = __ldg((const unsigned long long*)&g_Mtp[r * 32 + l]);
            asm("fma.rn.f32x2 %0, %1, %2, %0;" : "+l"(s2) : "l"(pp), "l"(mm));
        }
        float s0, s1;
        asm("mov.b64 {%0, %1}, %2;" : "=f"(s0), "=f"(s1) : "l"(s2));
        out[(size_t)(g0 + g) * O_ + l] = s0;
        out[(size_t)(g0 + g) * O_ + l + 32] = s1;
    }
}

extern "C" void kernel_launch(void* const* d_in, const int* in_sizes, int n_in,
                              void* d_out, int out_size) {
    const float* h  = (const float*)d_in[0];
    const float* W  = (const float*)d_in[1];
    const float* V  = (const float*)d_in[2];
    const float* Wl = (const float*)d_in[3];
    const float* bl = (const float*)d_in[4];
    float* out = (float*)d_out;

    static int attr_set = 0;
    if (!attr_set) {
        cudaFuncSetAttribute(main_kernel, cudaFuncAttributeMaxDynamicSharedMemorySize, SM_TOTAL);
        attr_set = 1;
    }

    prep_kernel<<<64, 256>>>(V, Wl, W);
    main_kernel<<<G_ / 16, 256, SM_TOTAL>>>(h, bl, out);
}

// round 10
// speedup vs baseline: 2.7674x; 1.1216x over previous
#include <cuda_runtime.h>
#include <cstdint>

#define G_ 16384
#define D_ 128
#define R_ 32
#define H_ 256
#define O_ 64

// B fragments, fragment-ordered: idx = (nt*16 + kg)*32 + lane, payload {bhi0,bhi1,blo0,blo1}
__device__ uint4  g_Bfrag[64 * 32];
__device__ float2 g_Mtp[R_ * 32];   // {Mt[r][o], Mt[r][o+32]}, Mt=(Wl@V)^T

__device__ __forceinline__ uint32_t cvt_tf32(float x) {
    uint32_t u;
    asm("cvt.rna.tf32.f32 %0, %1;" : "=r"(u) : "f"(x));
    return u;
}

// grid 64 x 256 = 16384 threads
__global__ void prep_kernel(const float* __restrict__ V,
                            const float* __restrict__ Wl,
                            const float* __restrict__ W) {
    int t = blockIdx.x * blockDim.x + threadIdx.x;
    if (t < 2048) {
        int l = t & 31, kg = (t >> 5) & 15, nt = t >> 9;
        int k0 = kg * 8 + (l & 3), n = nt * 8 + (l >> 2);
        float b0 = W[k0 * R_ + n];
        float b1 = W[(k0 + 4) * R_ + n];
        uint32_t h0 = __float_as_uint(b0) & 0xFFFFE000u;
        uint32_t h1 = __float_as_uint(b1) & 0xFFFFE000u;
        uint4 pk;
        pk.x = h0;
        pk.y = h1;
        pk.z = cvt_tf32(b0 - __uint_as_float(h0));
        pk.w = cvt_tf32(b1 - __uint_as_float(h1));
        g_Bfrag[t] = pk;
    }
    int u = t >> 3, seg = t & 7;
    int rr = u >> 6, rem = u & 63;
    const float* wl = Wl + rem * H_ + seg * 32;
    const float* vp = V + seg * 32 * R_ + rr;
    float acc = 0.f;
#pragma unroll
    for (int i = 0; i < 32; ++i)
        acc = fmaf(wl[i], vp[i * R_], acc);
#pragma unroll
    for (int m = 1; m <= 4; m <<= 1)
        acc += __shfl_xor_sync(0xffffffffu, acc, m);
    if (seg == 0)
        ((float*)g_Mtp)[rr * 64 + (rem & 31) * 2 + (rem >> 5)] = acc;
}

// ---- smem layout (bytes) ----
//  sB  [0, 32768)            64x32 uint4 B fragments
//  sA  32768 + w*10240       per warp: (buf*2+graph)*2560, each 32 rows x 20 floats
#define SA_OFF   32768
#define SM_TOTAL (32768 + 8 * 10240)   // 114688 B -> 2 CTAs/SM

__device__ __forceinline__ uint32_t smem_u32(const void* p) {
    uint32_t a;
    asm("{ .reg .u64 t; cvta.to.shared.u64 t, %1; cvt.u32.u64 %0, t; }" : "=r"(a) : "l"(p));
    return a;
}

#define MMA(c, a0, a1, a2, a3, b0, b1)                                        \
    asm volatile("mma.sync.aligned.m16n8k8.row.col.f32.tf32.tf32.f32 "        \
                 "{%0,%1,%2,%3}, {%4,%5,%6,%7}, {%8,%9}, {%0,%1,%2,%3};"      \
                 : "+f"(c[0]), "+f"(c[1]), "+f"(c[2]), "+f"(c[3])             \
                 : "r"(a0), "r"(a1), "r"(a2), "r"(a3), "r"(b0), "r"(b1))

#define CPASYNC(dst, src) \
    asm volatile("cp.async.cg.shared.global [%0], [%1], 16;" :: "r"(dst), "l"(src))

extern __shared__ __align__(16) char smc[];

// CTA = 8 warps, warp = 2 graphs, grid = 1024; target 2 CTAs/SM.
__global__ void __launch_bounds__(256, 2)
main_kernel(const float* __restrict__ hin, const float* __restrict__ bl,
            float* __restrict__ out) {
    const int t = threadIdx.x;
    const int w = t >> 5;
    const int l = t & 31;

    // ---- stage B fragments (whole CTA) ----
    {
        uint4* sB = (uint4*)smc;
#pragma unroll
        for (int j = 0; j < 8; ++j) sB[j * 256 + t] = g_Bfrag[j * 256 + t];
    }
    __syncthreads();

    float* sA = (float*)(smc + SA_OFF + w * 10240);
    const uint32_t sAu = smem_u32(sA);

    const int g0 = blockIdx.x * 16 + w * 2;
    const float* hb[2];
    hb[0] = hin + (size_t)g0 * (32 * D_);
    hb[1] = hb[0] + 32 * D_;

    const int r4 = l >> 2, lc = l & 3;
    const int srow = l >> 2, sc = (l & 3) * 4;   // staging: 8 rows x 4 float4-cols

    float c[2][2][4][4];
#pragma unroll
    for (int g = 0; g < 2; ++g)
#pragma unroll
        for (int mt = 0; mt < 2; ++mt)
#pragma unroll
            for (int nt = 0; nt < 4; ++nt)
#pragma unroll
                for (int i = 0; i < 4; ++i) c[g][mt][nt][i] = 0.f;

    // ---- stage chunk 0 (16 k-cols) into buf 0 ----
#pragma unroll
    for (int g = 0; g < 2; ++g) {
        uint32_t dbase = sAu + g * 2560;
        const float* src = hb[g];
#pragma unroll
        for (int j = 0; j < 4; ++j) {
            int row = j * 8 + srow;
            CPASYNC(dbase + (row * 20 + sc) * 4, src + row * D_ + sc);
        }
    }
    asm volatile("cp.async.commit_group;" ::: "memory");

#pragma unroll 1
    for (int ch = 0; ch < 8; ++ch) {
        const int buf = ch & 1;
        if (ch < 7) {
            const int nbuf = buf ^ 1;
#pragma unroll
            for (int g = 0; g < 2; ++g) {
                uint32_t dbase = sAu + (nbuf * 2 + g) * 2560;
                const float* src = hb[g] + (ch + 1) * 16;
#pragma unroll
                for (int j = 0; j < 4; ++j) {
                    int row = j * 8 + srow;
                    CPASYNC(dbase + (row * 20 + sc) * 4, src + row * D_ + sc);
                }
            }
            asm volatile("cp.async.commit_group;" ::: "memory");
            asm volatile("cp.async.wait_group 1;" ::: "memory");
        } else {
            asm volatile("cp.async.wait_group 0;" ::: "memory");
        }
        __syncwarp();

        const float* A[2];
        A[0] = sA + (buf * 2 + 0) * 640;
        A[1] = sA + (buf * 2 + 1) * 640;

#pragma unroll
        for (int ksl = 0; ksl < 2; ++ksl) {
            const int kc = ksl * 8 + lc;
            const int kg = ch * 2 + ksl;
            uint4 bv[4];
#pragma unroll
            for (int nt = 0; nt < 4; ++nt)
                bv[nt] = ((const uint4*)smc)[nt * 512 + kg * 32 + l];

#pragma unroll
            for (int g = 0; g < 2; ++g) {
                uint32_t ahi[2][4], alo[2][4];
#pragma unroll
                for (int mt = 0; mt < 2; ++mt) {
                    const float* ab = A[g] + (mt * 16 + r4) * 20;
                    float a0 = ab[kc];
                    float a1 = ab[8 * 20 + kc];
                    float a2 = ab[kc + 4];
                    float a3 = ab[8 * 20 + kc + 4];
                    ahi[mt][0] = __float_as_uint(a0) & 0xFFFFE000u;
                    ahi[mt][1] = __float_as_uint(a1) & 0xFFFFE000u;
                    ahi[mt][2] = __float_as_uint(a2) & 0xFFFFE000u;
                    ahi[mt][3] = __float_as_uint(a3) & 0xFFFFE000u;
                    alo[mt][0] = cvt_tf32(a0 - __uint_as_float(ahi[mt][0]));
                    alo[mt][1] = cvt_tf32(a1 - __uint_as_float(ahi[mt][1]));
                    alo[mt][2] = cvt_tf32(a2 - __uint_as_float(ahi[mt][2]));
                    alo[mt][3] = cvt_tf32(a3 - __uint_as_float(ahi[mt][3]));
                }
#pragma unroll
                for (int mt = 0; mt < 2; ++mt)
#pragma unroll
                    for (int nt = 0; nt < 4; ++nt) {
                        MMA(c[g][mt][nt], ahi[mt][0], ahi[mt][1], ahi[mt][2], ahi[mt][3],
                            bv[nt].x, bv[nt].y);
                        MMA(c[g][mt][nt], ahi[mt][0], ahi[mt][1], ahi[mt][2], ahi[mt][3],
                            bv[nt].z, bv[nt].w);
                        MMA(c[g][mt][nt], alo[mt][0], alo[mt][1], alo[mt][2], alo[mt][3],
                            bv[nt].x, bv[nt].y);
                    }
            }
        }
        __syncwarp();
    }

    // ---- pooling: product over all 32 nodes, kept in registers ----
    // After 3 XOR rounds every lane holds pooled for cols nt*8 + 2*lc + b.
    float pv[2][8];
#pragma unroll
    for (int g = 0; g < 2; ++g) {
#pragma unroll
        for (int nt = 0; nt < 4; ++nt)
#pragma unroll
            for (int b = 0; b < 2; ++b)
                pv[g][nt * 2 + b] = c[g][0][nt][b] * c[g][0][nt][b + 2] *
                                    c[g][1][nt][b] * c[g][1][nt][b + 2];
#pragma unroll
        for (int m = 4; m <= 16; m <<= 1)
#pragma unroll
            for (int i = 0; i < 8; ++i)
                pv[g][i] *= __shfl_xor_sync(0xffffffffu, pv[g][i], m);
    }

    // ---- epilogue: score[o] = bl[o] + sum_r pooled[r]*Mt[r][o]; lane -> (o, o+32) ----
    float b0 = bl[l], b1 = bl[l + 32];
#pragma unroll 1
    for (int g = 0; g < 2; ++g) {
        unsigned long long s2;
        asm("mov.b64 %0, {%1, %2};" : "=l"(s2) : "f"(b0), "f"(b1));
#pragma unroll
        for (int r = 0; r < R_; ++r) {
            // pooled[r] lives at lane (r&7)>>1, register index (r>>3)*2 + (r&1)
            float pvv = __shfl_sync(0xffffffffu, pv[g][(r >> 3) * 2 + (r & 1)], (r & 7) >> 1);
            unsigned long long pp, mm;
            asm("mov.b64 %0, {%1, %1};" : "=l"(pp) : "f"(pvv));
            mm = __ldg((const unsigned long long*)&g_Mtp[r * 32 + l]);
            asm("fma.rn.f32x2 %0, %1, %2, %0;" : "+l"(s2) : "l"(pp), "l"(mm));
        }
        float s0, s1;
        asm("mov.b64 {%0, %1}, %2;" : "=f"(s0), "=f"(s1) : "l"(s2));
        out[(size_t)(g0 + g) * O_ + l] = s0;
        out[(size_t)(g0 + g) * O_ + l + 32] = s1;
    }
}

extern "C" void kernel_launch(void* const* d_in, const int* in_sizes, int n_in,
                              void* d_out, int out_size) {
    const float* h  = (const float*)d_in[0];
    const float* W  = (const float*)d_in[1];
    const float* V  = (const float*)d_in[2];
    const float* Wl = (const float*)d_in[3];
    const float* bl = (const float*)d_in[4];
    float* out = (float*)d_out;

    static int attr_set = 0;
    if (!attr_set) {
        cudaFuncSetAttribute(main_kernel, cudaFuncAttributeMaxDynamicSharedMemorySize, SM_TOTAL);
        attr_set = 1;
    }

    prep_kernel<<<64, 256>>>(V, Wl, W);
    main_kernel<<<G_ / 16, 256, SM_TOTAL>>>(h, bl, out);
}

// round 12
// speedup vs baseline: 3.7611x; 1.3591x over previous
#include <cuda_runtime.h>
#include <cstdint>

#define G_ 16384
#define D_ 128
#define R_ 32
#define H_ 256
#define O_ 64

// B fragments fp16: idx = (nt*8 + kg)*32 + lane, payload {bhi0, bhi1, blo0, blo1}
__device__ uint4  g_Bfrag[32 * 32];
__device__ float2 g_Mtp[R_ * 32];   // {Mt[r][o], Mt[r][o+32]}, Mt=(Wl@V)^T

// pack two floats -> f16x2 (x0 -> low half / element k, x1 -> high half / k+1)
__device__ __forceinline__ uint32_t pack2(float x0, float x1) {
    uint32_t r;
    asm("cvt.rn.f16x2.f32 %0, %1, %2;" : "=r"(r) : "f"(x1), "f"(x0));
    return r;
}
__device__ __forceinline__ float2 unpack2(uint32_t h) {
    float lo, hi;
    asm("{.reg .b16 l, h; mov.b32 {l, h}, %2; cvt.f32.f16 %0, l; cvt.f32.f16 %1, h;}"
        : "=f"(lo), "=f"(hi) : "r"(h));
    return make_float2(lo, hi);
}

// grid 64 x 256 = 16384 threads
__global__ void prep_kernel(const float* __restrict__ V,
                            const float* __restrict__ Wl,
                            const float* __restrict__ W) {
    int t = blockIdx.x * blockDim.x + threadIdx.x;
    if (t < 1024) {
        int l = t & 31, kg = (t >> 5) & 7, nt = t >> 8;
        int k0 = kg * 16 + (l & 3) * 2;
        int n = nt * 8 + (l >> 2);
        float b00 = W[k0 * R_ + n],       b01 = W[(k0 + 1) * R_ + n];
        float b10 = W[(k0 + 8) * R_ + n], b11 = W[(k0 + 9) * R_ + n];
        uint4 pk;
        pk.x = pack2(b00, b01);
        pk.y = pack2(b10, b11);
        float2 f0 = unpack2(pk.x), f1 = unpack2(pk.y);
        pk.z = pack2(b00 - f0.x, b01 - f0.y);
        pk.w = pack2(b10 - f1.x, b11 - f1.y);
        g_Bfrag[t] = pk;
    }
    int u = t >> 3, seg = t & 7;
    int rr = u >> 6, rem = u & 63;
    const float* wl = Wl + rem * H_ + seg * 32;
    const float* vp = V + seg * 32 * R_ + rr;
    float acc = 0.f;
#pragma unroll
    for (int i = 0; i < 32; ++i)
        acc = fmaf(wl[i], vp[i * R_], acc);
#pragma unroll
    for (int m = 1; m <= 4; m <<= 1)
        acc += __shfl_xor_sync(0xffffffffu, acc, m);
    if (seg == 0)
        ((float*)g_Mtp)[rr * 64 + (rem & 31) * 2 + (rem >> 5)] = acc;
}

// ---- smem layout (bytes) ----
//  sB  [0, 16384)          32x32 uint4 B fragments
//  sA  16384 + w*7680      per warp: 3 ring buffers x (32 rows x 20 floats) = 3 x 2560 B
#define SA_OFF   16384
#define SM_TOTAL (16384 + 8 * 7680)   // 77824 B

__device__ __forceinline__ uint32_t smem_u32(const void* p) {
    uint32_t a;
    asm("{ .reg .u64 t; cvta.to.shared.u64 t, %1; cvt.u32.u64 %0, t; }" : "=r"(a) : "l"(p));
    return a;
}

#define MMAH(c, a0, a1, a2, a3, b0, b1)                                        \
    asm volatile("mma.sync.aligned.m16n8k16.row.col.f32.f16.f16.f32 "          \
                 "{%0,%1,%2,%3}, {%4,%5,%6,%7}, {%8,%9}, {%0,%1,%2,%3};"       \
                 : "+f"(c[0]), "+f"(c[1]), "+f"(c[2]), "+f"(c[3])              \
                 : "r"(a0), "r"(a1), "r"(a2), "r"(a3), "r"(b0), "r"(b1))

#define CPASYNC(dst, src) \
    asm volatile("cp.async.cg.shared.global [%0], [%1], 16;" :: "r"(dst), "l"(src))
#define CPCOMMIT() asm volatile("cp.async.commit_group;" ::: "memory")
#define CPWAIT(n)  asm volatile("cp.async.wait_group %0;" :: "n"(n) : "memory")

extern __shared__ __align__(16) char smc[];

// CTA = 8 warps, warp = 1 graph, grid = 2048; 2 CTAs/SM.
__global__ void __launch_bounds__(256, 2)
main_kernel(const float* __restrict__ hin, const float* __restrict__ bl,
            float* __restrict__ out) {
    const int t = threadIdx.x;
    const int w = t >> 5;
    const int l = t & 31;

    // ---- stage B fragments (whole CTA) ----
    {
        uint4* sB = (uint4*)smc;
#pragma unroll
        for (int j = 0; j < 4; ++j) sB[j * 256 + t] = g_Bfrag[j * 256 + t];
    }
    __syncthreads();

    float* sA = (float*)(smc + SA_OFF + w * 7680);
    const uint32_t sAu = smem_u32(sA);

    const int g = blockIdx.x * 8 + w;
    const float* hb = hin + (size_t)g * (32 * D_);

    const int r4 = l >> 2, lc = l & 3;
    const int srow = l >> 2, sc = (l & 3) * 4;   // staging: rows j*8+srow, 4 float cols

    float c[2][4][4];
#pragma unroll
    for (int mt = 0; mt < 2; ++mt)
#pragma unroll
        for (int nt = 0; nt < 4; ++nt)
#pragma unroll
            for (int i = 0; i < 4; ++i) c[mt][nt][i] = 0.f;

    // ---- prologue: fill ring with chunks 0,1,2 ----
#pragma unroll
    for (int ch = 0; ch < 3; ++ch) {
        uint32_t dbase = sAu + ch * 2560;
        const float* src = hb + ch * 16;
#pragma unroll
        for (int j = 0; j < 4; ++j) {
            int row = j * 8 + srow;
            CPASYNC(dbase + (row * 20 + sc) * 4, src + row * D_ + sc);
        }
        CPCOMMIT();
    }

#pragma unroll
    for (int kg = 0; kg < 8; ++kg) {
        const int buf = kg % 3;
        // Drain so that chunk kg is guaranteed complete (commits stop at chunk 7):
        if (kg <= 5)      CPWAIT(2);
        else if (kg == 6) CPWAIT(1);
        else              CPWAIT(0);
        __syncwarp();

        // B fragments for this k16 step
        uint4 bv[4];
#pragma unroll
        for (int nt = 0; nt < 4; ++nt)
            bv[nt] = ((const uint4*)smc)[(nt * 8 + kg) * 32 + l];

        // A raw pairs + split to fp16 hi/lo fragments
        const float* A = sA + buf * 640;
        uint32_t ahi[2][4], alo[2][4];
#pragma unroll
        for (int mt = 0; mt < 2; ++mt) {
            const float* r0 = A + (mt * 16 + r4) * 20 + 2 * lc;
            const float* r1 = r0 + 8 * 20;
            float2 p0 = *(const float2*)(r0);
            float2 p1 = *(const float2*)(r1);
            float2 p2 = *(const float2*)(r0 + 8);
            float2 p3 = *(const float2*)(r1 + 8);
            ahi[mt][0] = pack2(p0.x, p0.y);
            ahi[mt][1] = pack2(p1.x, p1.y);
            ahi[mt][2] = pack2(p2.x, p2.y);
            ahi[mt][3] = pack2(p3.x, p3.y);
            float2 f;
            f = unpack2(ahi[mt][0]); alo[mt][0] = pack2(p0.x - f.x, p0.y - f.y);
            f = unpack2(ahi[mt][1]); alo[mt][1] = pack2(p1.x - f.x, p1.y - f.y);
            f = unpack2(ahi[mt][2]); alo[mt][2] = pack2(p2.x - f.x, p2.y - f.y);
            f = unpack2(ahi[mt][3]); alo[mt][3] = pack2(p3.x - f.x, p3.y - f.y);
        }
        __syncwarp();   // all lanes consumed chunk -> safe to overwrite

        // refill this buffer with chunk kg+3
        if (kg + 3 < 8) {
            uint32_t dbase = sAu + buf * 2560;
            const float* src = hb + (kg + 3) * 16;
#pragma unroll
            for (int j = 0; j < 4; ++j) {
                int row = j * 8 + srow;
                CPASYNC(dbase + (row * 20 + sc) * 4, src + row * D_ + sc);
            }
            CPCOMMIT();
        }

        // 24 MMAs: hi*bhi + hi*blo + lo*bhi
#pragma unroll
        for (int mt = 0; mt < 2; ++mt)
#pragma unroll
            for (int nt = 0; nt < 4; ++nt) {
                MMAH(c[mt][nt], ahi[mt][0], ahi[mt][1], ahi[mt][2], ahi[mt][3],
                     bv[nt].x, bv[nt].y);
                MMAH(c[mt][nt], ahi[mt][0], ahi[mt][1], ahi[mt][2], ahi[mt][3],
                     bv[nt].z, bv[nt].w);
                MMAH(c[mt][nt], alo[mt][0], alo[mt][1], alo[mt][2], alo[mt][3],
                     bv[nt].x, bv[nt].y);
            }
    }

    // ---- pooling: product over 32 nodes, all in registers ----
    float pv[8];
#pragma unroll
    for (int nt = 0; nt < 4; ++nt)
#pragma unroll
        for (int b = 0; b < 2; ++b)
            pv[nt * 2 + b] = c[0][nt][b] * c[0][nt][b + 2] *
                             c[1][nt][b] * c[1][nt][b + 2];
#pragma unroll
    for (int m = 4; m <= 16; m <<= 1)
#pragma unroll
        for (int i = 0; i < 8; ++i)
            pv[i] *= __shfl_xor_sync(0xffffffffu, pv[i], m);

    // ---- epilogue: score[o] = bl[o] + sum_r pooled[r]*Mt[r][o]; lane -> (o, o+32) ----
    unsigned long long s2;
    {
        float b0 = bl[l], b1 = bl[l + 32];
        asm("mov.b64 %0, {%1, %2};" : "=l"(s2) : "f"(b0), "f"(b1));
    }
#pragma unroll
    for (int r = 0; r < R_; ++r) {
        float pvv = __shfl_sync(0xffffffffu, pv[(r >> 3) * 2 + (r & 1)], (r & 7) >> 1);
        unsigned long long pp, mm;
        asm("mov.b64 %0, {%1, %1};" : "=l"(pp) : "f"(pvv));
        mm = __ldg((const unsigned long long*)&g_Mtp[r * 32 + l]);
        asm("fma.rn.f32x2 %0, %1, %2, %0;" : "+l"(s2) : "l"(pp), "l"(mm));
    }
    float s0, s1;
    asm("mov.b64 {%0, %1}, %2;" : "=f"(s0), "=f"(s1) : "l"(s2));
    out[(size_t)g * O_ + l] = s0;
    out[(size_t)g * O_ + l + 32] = s1;
}

extern "C" void kernel_launch(void* const* d_in, const int* in_sizes, int n_in,
                              void* d_out, int out_size) {
    const float* h  = (const float*)d_in[0];
    const float* W  = (const float*)d_in[1];
    const float* V  = (const float*)d_in[2];
    const float* Wl = (const float*)d_in[3];
    const float* bl = (const float*)d_in[4];
    float* out = (float*)d_out;

    static int attr_set = 0;
    if (!attr_set) {
        cudaFuncSetAttribute(main_kernel, cudaFuncAttributeMaxDynamicSharedMemorySize, SM_TOTAL);
        attr_set = 1;
    }

    prep_kernel<<<64, 256>>>(V, Wl, W);
    main_kernel<<<G_ / 8, 256, SM_TOTAL>>>(h, bl, out);
}

// round 13
// speedup vs baseline: 3.8777x; 1.0310x over previous
#include <cuda_runtime.h>
#include <cstdint>

#define G_ 16384
#define D_ 128
#define R_ 32
#define H_ 256
#define O_ 64

// B fragments fp16: idx = (nt*8 + kg)*32 + lane, payload {bhi0, bhi1, blo0, blo1}
__device__ uint4  g_Bfrag[32 * 32];
__device__ float2 g_Mtp[R_ * 32];   // {Mt[r][o], Mt[r][o+32]}, Mt=(Wl@V)^T

// pack two floats -> f16x2 (x0 -> low half / element k, x1 -> high half / k+1)
__device__ __forceinline__ uint32_t pack2(float x0, float x1) {
    uint32_t r;
    asm("cvt.rn.f16x2.f32 %0, %1, %2;" : "=r"(r) : "f"(x1), "f"(x0));
    return r;
}
__device__ __forceinline__ float2 unpack2(uint32_t h) {
    float lo, hi;
    asm("{.reg .b16 l, h; mov.b32 {l, h}, %2; cvt.f32.f16 %0, l; cvt.f32.f16 %1, h;}"
        : "=f"(lo), "=f"(hi) : "r"(h));
    return make_float2(lo, hi);
}

// grid 64 x 256 = 16384 threads
__global__ void prep_kernel(const float* __restrict__ V,
                            const float* __restrict__ Wl,
                            const float* __restrict__ W) {
    int t = blockIdx.x * blockDim.x + threadIdx.x;
    if (t < 1024) {
        int l = t & 31, kg = (t >> 5) & 7, nt = t >> 8;
        int k0 = kg * 16 + (l & 3) * 2;
        int n = nt * 8 + (l >> 2);
        float b00 = W[k0 * R_ + n],       b01 = W[(k0 + 1) * R_ + n];
        float b10 = W[(k0 + 8) * R_ + n], b11 = W[(k0 + 9) * R_ + n];
        uint4 pk;
        pk.x = pack2(b00, b01);
        pk.y = pack2(b10, b11);
        float2 f0 = unpack2(pk.x), f1 = unpack2(pk.y);
        pk.z = pack2(b00 - f0.x, b01 - f0.y);
        pk.w = pack2(b10 - f1.x, b11 - f1.y);
        g_Bfrag[t] = pk;
    }
    int u = t >> 3, seg = t & 7;
    int rr = u >> 6, rem = u & 63;
    const float* wl = Wl + rem * H_ + seg * 32;
    const float* vp = V + seg * 32 * R_ + rr;
    float acc = 0.f;
#pragma unroll
    for (int i = 0; i < 32; ++i)
        acc = fmaf(wl[i], vp[i * R_], acc);
#pragma unroll
    for (int m = 1; m <= 4; m <<= 1)
        acc += __shfl_xor_sync(0xffffffffu, acc, m);
    if (seg == 0)
        ((float*)g_Mtp)[rr * 64 + (rem & 31) * 2 + (rem >> 5)] = acc;
}

// ---- smem layout (bytes) ----
//  sB  [0, 16384)          32x32 uint4 B fragments
//  sA  16384 + w*10240     per warp: 4 ring buffers x (32 rows x 20 floats) = 4 x 2560 B
#define SA_OFF   16384
#define SM_TOTAL (16384 + 8 * 10240)   // 98304 B -> 2 CTAs/SM

__device__ __forceinline__ uint32_t smem_u32(const void* p) {
    uint32_t a;
    asm("{ .reg .u64 t; cvta.to.shared.u64 t, %1; cvt.u32.u64 %0, t; }" : "=r"(a) : "l"(p));
    return a;
}

#define MMAH(c, a0, a1, a2, a3, b0, b1)                                        \
    asm volatile("mma.sync.aligned.m16n8k16.row.col.f32.f16.f16.f32 "          \
                 "{%0,%1,%2,%3}, {%4,%5,%6,%7}, {%8,%9}, {%0,%1,%2,%3};"       \
                 : "+f"(c[0]), "+f"(c[1]), "+f"(c[2]), "+f"(c[3])              \
                 : "r"(a0), "r"(a1), "r"(a2), "r"(a3), "r"(b0), "r"(b1))

#define CPASYNC(dst, src) \
    asm volatile("cp.async.cg.shared.global [%0], [%1], 16;" :: "r"(dst), "l"(src))
#define CPCOMMIT() asm volatile("cp.async.commit_group;" ::: "memory")
#define CPWAIT(n)  asm volatile("cp.async.wait_group %0;" :: "n"(n) : "memory")

extern __shared__ __align__(16) char smc[];

// CTA = 8 warps, warp = 1 graph, grid = 2048; 2 CTAs/SM.
__global__ void __launch_bounds__(256, 2)
main_kernel(const float* __restrict__ hin, const float* __restrict__ bl,
            float* __restrict__ out) {
    const int t = threadIdx.x;
    const int w = t >> 5;
    const int l = t & 31;

    // ---- stage B fragments (whole CTA) ----
    {
        uint4* sB = (uint4*)smc;
#pragma unroll
        for (int j = 0; j < 4; ++j) sB[j * 256 + t] = g_Bfrag[j * 256 + t];
    }
    __syncthreads();

    float* sA = (float*)(smc + SA_OFF + w * 10240);
    const uint32_t sAu = smem_u32(sA);

    const int g = blockIdx.x * 8 + w;
    const float* hb = hin + (size_t)g * (32 * D_);

    const int r4 = l >> 2, lc = l & 3;
    const int srow = l >> 2, sc = (l & 3) * 4;   // staging: rows j*8+srow, 4 float cols

    float c[2][4][4];
#pragma unroll
    for (int mt = 0; mt < 2; ++mt)
#pragma unroll
        for (int nt = 0; nt < 4; ++nt)
#pragma unroll
            for (int i = 0; i < 4; ++i) c[mt][nt][i] = 0.f;

    // ---- prologue: fill ring with chunks 0,1,2 ----
#pragma unroll
    for (int ch = 0; ch < 3; ++ch) {
        uint32_t dbase = sAu + ch * 2560;
        const float* src = hb + ch * 16;
#pragma unroll
        for (int j = 0; j < 4; ++j) {
            int row = j * 8 + srow;
            CPASYNC(dbase + (row * 20 + sc) * 4, src + row * D_ + sc);
        }
        CPCOMMIT();
    }

#pragma unroll
    for (int kg = 0; kg < 8; ++kg) {
        // Refill FIRST (buffer (kg+3)%4 was fully consumed at iteration kg-1;
        // the converged mma.sync there guarantees all lanes are done with it).
        if (kg + 3 < 8) {
            uint32_t dbase = sAu + ((kg + 3) & 3) * 2560;
            const float* src = hb + (kg + 3) * 16;
#pragma unroll
            for (int j = 0; j < 4; ++j) {
                int row = j * 8 + srow;
                CPASYNC(dbase + (row * 20 + sc) * 4, src + row * D_ + sc);
            }
            CPCOMMIT();
        }
        // Drain so chunk kg is complete. Outstanding after chunk kg: min(7,kg+3)-kg.
        if (kg <= 4)      CPWAIT(3);
        else if (kg == 5) CPWAIT(2);
        else if (kg == 6) CPWAIT(1);
        else              CPWAIT(0);
        __syncwarp();

        // B fragments for this k16 step
        uint4 bv[4];
#pragma unroll
        for (int nt = 0; nt < 4; ++nt)
            bv[nt] = ((const uint4*)smc)[(nt * 8 + kg) * 32 + l];

        // A raw pairs + split to fp16 hi/lo fragments
        const float* A = sA + (kg & 3) * 640;
        uint32_t ahi[2][4], alo[2][4];
#pragma unroll
        for (int mt = 0; mt < 2; ++mt) {
            const float* r0 = A + (mt * 16 + r4) * 20 + 2 * lc;
            const float* r1 = r0 + 8 * 20;
            float2 p0 = *(const float2*)(r0);
            float2 p1 = *(const float2*)(r1);
            float2 p2 = *(const float2*)(r0 + 8);
            float2 p3 = *(const float2*)(r1 + 8);
            ahi[mt][0] = pack2(p0.x, p0.y);
            ahi[mt][1] = pack2(p1.x, p1.y);
            ahi[mt][2] = pack2(p2.x, p2.y);
            ahi[mt][3] = pack2(p3.x, p3.y);
            float2 f;
            f = unpack2(ahi[mt][0]); alo[mt][0] = pack2(p0.x - f.x, p0.y - f.y);
            f = unpack2(ahi[mt][1]); alo[mt][1] = pack2(p1.x - f.x, p1.y - f.y);
            f = unpack2(ahi[mt][2]); alo[mt][2] = pack2(p2.x - f.x, p2.y - f.y);
            f = unpack2(ahi[mt][3]); alo[mt][3] = pack2(p3.x - f.x, p3.y - f.y);
        }

        // 24 MMAs: hi*bhi + hi*blo + lo*bhi
#pragma unroll
        for (int mt = 0; mt < 2; ++mt)
#pragma unroll
            for (int nt = 0; nt < 4; ++nt) {
                MMAH(c[mt][nt], ahi[mt][0], ahi[mt][1], ahi[mt][2], ahi[mt][3],
                     bv[nt].x, bv[nt].y);
                MMAH(c[mt][nt], ahi[mt][0], ahi[mt][1], ahi[mt][2], ahi[mt][3],
                     bv[nt].z, bv[nt].w);
                MMAH(c[mt][nt], alo[mt][0], alo[mt][1], alo[mt][2], alo[mt][3],
                     bv[nt].x, bv[nt].y);
            }
    }

    // ---- pooling: product over 32 nodes, all in registers ----
    float pv[8];
#pragma unroll
    for (int nt = 0; nt < 4; ++nt)
#pragma unroll
        for (int b = 0; b < 2; ++b)
            pv[nt * 2 + b] = c[0][nt][b] * c[0][nt][b + 2] *
                             c[1][nt][b] * c[1][nt][b + 2];
#pragma unroll
    for (int m = 4; m <= 16; m <<= 1)
#pragma unroll
        for (int i = 0; i < 8; ++i)
            pv[i] *= __shfl_xor_sync(0xffffffffu, pv[i], m);

    // ---- epilogue: score[o] = bl[o] + sum_r pooled[r]*Mt[r][o]; lane -> (o, o+32) ----
    unsigned long long s2;
    {
        float b0 = bl[l], b1 = bl[l + 32];
        asm("mov.b64 %0, {%1, %2};" : "=l"(s2) : "f"(b0), "f"(b1));
    }
#pragma unroll
    for (int r = 0; r < R_; ++r) {
        float pvv = __shfl_sync(0xffffffffu, pv[(r >> 3) * 2 + (r & 1)], (r & 7) >> 1);
        unsigned long long pp, mm;
        asm("mov.b64 %0, {%1, %1};" : "=l"(pp) : "f"(pvv));
        mm = __ldg((const unsigned long long*)&g_Mtp[r * 32 + l]);
        asm("fma.rn.f32x2 %0, %1, %2, %0;" : "+l"(s2) : "l"(pp), "l"(mm));
    }
    float s0, s1;
    asm("mov.b64 {%0, %1}, %2;" : "=f"(s0), "=f"(s1) : "l"(s2));
    out[(size_t)g * O_ + l] = s0;
    out[(size_t)g * O_ + l + 32] = s1;
}

extern "C" void kernel_launch(void* const* d_in, const int* in_sizes, int n_in,
                              void* d_out, int out_size) {
    const float* h  = (const float*)d_in[0];
    const float* W  = (const float*)d_in[1];
    const float* V  = (const float*)d_in[2];
    const float* Wl = (const float*)d_in[3];
    const float* bl = (const float*)d_in[4];
    float* out = (float*)d_out;

    static int attr_set = 0;
    if (!attr_set) {
        cudaFuncSetAttribute(main_kernel, cudaFuncAttributeMaxDynamicSharedMemorySize, SM_TOTAL);
        attr_set = 1;
    }

    prep_kernel<<<64, 256>>>(V, Wl, W);
    main_kernel<<<G_ / 8, 256, SM_TOTAL>>>(h, bl, out);
}